// round 15
// baseline (speedup 1.0000x reference)
#include <cuda_runtime.h>
#include <stdint.h>

#define TABLE_MASK 0x7FFFFu
#define NRED 32
#define FULLM 0xffffffffu
#define NRAY 8

// Low 19 bits of ((c+1) * PIS[c]) — the only bits that matter for
// tidx = (idx ^ PP) & (2^19-1), since idx >= 0 and XOR is bitwise.
__constant__ unsigned c_ppl[8] = {
    (unsigned)(774363409ull   & 0x7FFFFull),
    (unsigned)(5308871522ull  & 0x7FFFFull),
    (unsigned)(2416379583ull  & 0x7FFFFull),
    (unsigned)(400000028ull   & 0x7FFFFull),
    (unsigned)(1671816955ull  & 0x7FFFFull),
    (unsigned)(8006180478ull  & 0x7FFFFull),
    (unsigned)(5140543849ull  & 0x7FFFFull),
    (unsigned)(17074907144ull & 0x7FFFFull)
};

static __device__ int g_partial[NRED];
static __device__ int g_activeL;
static __device__ unsigned g_ticket;

#define CP_ASYNC16(dst_smem, src_gmem)                                   \
    asm volatile("cp.async.cg.shared.global [%0], [%1], 16;"             \
                 :: "r"(dst_smem), "l"(src_gmem))
#define CP_COMMIT() asm volatile("cp.async.commit_group;" ::: "memory")
template <int N>
__device__ __forceinline__ void cp_wait() {
    asm volatile("cp.async.wait_group %0;" :: "n"(N) : "memory");
}

// ---------------------------------------------------------------------------
// Kernel 1: grid max over depth -> g_activeL (last block folds partials)
// ---------------------------------------------------------------------------
__global__ void depth_reduce_kernel(const int* __restrict__ depth, int n) {
    int m = 0;
    for (int i = blockIdx.x * blockDim.x + threadIdx.x; i < n;
         i += gridDim.x * blockDim.x)
        m = max(m, depth[i]);
    #pragma unroll
    for (int s = 16; s > 0; s >>= 1)
        m = max(m, __shfl_xor_sync(FULLM, m, s));
    __shared__ int sm[32];
    __shared__ bool last;
    int w = threadIdx.x >> 5;
    if ((threadIdx.x & 31) == 0) sm[w] = m;
    __syncthreads();
    if (threadIdx.x == 0) {
        int nw = (blockDim.x + 31) >> 5;
        int mm = sm[0];
        for (int i = 1; i < nw; i++) mm = max(mm, sm[i]);
        g_partial[blockIdx.x] = mm;
        __threadfence();
        unsigned t = atomicAdd(&g_ticket, 1u);
        last = (t == (unsigned)(gridDim.x - 1));
    }
    __syncthreads();
    if (last && threadIdx.x < 32) {
        int mm = g_partial[threadIdx.x];
        #pragma unroll
        for (int s = 16; s > 0; s >>= 1)
            mm = max(mm, __shfl_xor_sync(FULLM, mm, s));
        if (threadIdx.x == 0) {
            g_activeL = (mm < 8) ? mm : 8;
            g_ticket = 0;                 // reset for graph replay
        }
    }
}

// ---------------------------------------------------------------------------
// Kernel 2: main encoding, NRAY=8 rays/block, warp = level.
// Feature gather via cp.async into a 4-slot smem ring, prefetch depth 3:
// at iteration j, the gathers for stages j+1, j+2, j+3 are in flight while
// stage j computes (slot reuse distance 4 keeps depth-3 WAR-safe — the slot
// GATHER(j+3) overwrites was consumed at iteration j-1).
// Node boxes (+reciprocals) and padded coords staged once per block in smem;
// steady state reads them as 4 broadcast LDS.128 per stage.
// ---------------------------------------------------------------------------
__global__ void __launch_bounds__(256, 6) nbvh_main_kernel(
    const float* __restrict__ inp,          // [R,16,3]
    const int*   __restrict__ history,      // [R,64]
    const float* __restrict__ nodes_min,    // [N,3]
    const float* __restrict__ nodes_extent, // [N,3]
    const float* __restrict__ emb,          // [524288,16]
    float* __restrict__ out,                // [R, 8*16*16]
    int R)
{
    __shared__ float4 sfeat[8][4][32];     // [warp][ring][corner*4+dim_group]
    __shared__ float4 s_inp4[NRAY * 16];   // [ray*16 + point] = {x,y,z,_}
    __shared__ float4 s_box[NRAY][8][2];   // [ray][level]

    const int tid  = threadIdx.x;
    const int w    = tid >> 5;       // level l
    const int lane = tid & 31;
    const int r0   = blockIdx.x * NRAY;

    // --- stage coords: thread t < 128 handles one point, padded to float4 ---
    if (tid < NRAY * 16) {
        int rj = r0 + (tid >> 4); if (rj >= R) rj = R - 1;
        const float* src = inp + (size_t)rj * 48 + (tid & 15) * 3;
        s_inp4[tid] = make_float4(src[0], src[1], src[2], 0.0f);
    }
    // --- stage node boxes: thread t < 64 handles one (ray, level) pair ---
    if (tid < NRAY * 8) {
        const int j = tid >> 3, lv = tid & 7;
        int rj = r0 + j; if (rj >= R) rj = R - 1;
        const int bi = history[rj * 64 + lv];
        const float* nm = nodes_min    + (size_t)bi * 3;
        const float* ne = nodes_extent + (size_t)bi * 3;
        s_box[j][lv][0] = make_float4(nm[0], nm[1], nm[2],
                                      __fdividef(1.0f, ne[0]));
        s_box[j][lv][1] = make_float4(__fdividef(1.0f, ne[1]),
                                      __fdividef(1.0f, ne[2]), 0.0f, 0.0f);
    }

    const int activeL = g_activeL;     // uniform scalar
    const float act   = (w < activeL) ? 1.0f : 0.0f;

    // All NRAY history indices up-front (MLP=8), register-resident —
    // keeps the cp.async address path free of LDS latency.
    int idxs[NRAY];
    #pragma unroll
    for (int j = 0; j < NRAY; j++) {
        int rj = r0 + j; if (rj >= R) rj = R - 1;
        idxs[j] = history[rj * 64 + w];
    }

    const int c_   = lane >> 2;      // corner for gather
    const int sub_ = lane & 3;       // float4 sub for gather
    const unsigned ppl = c_ppl[c_];  // low-19-bit hash constant
    const float4* e4 = reinterpret_cast<const float4*>(emb);

    const unsigned smem_lane_base =
        (unsigned)__cvta_generic_to_shared(&sfeat[w][0][lane]);
#define GATHER(stage)                                                        \
    {                                                                        \
        const unsigned tixg = ((unsigned)idxs[stage] ^ ppl) & TABLE_MASK;    \
        CP_ASYNC16(smem_lane_base + ((stage) & 3) * (32 * 16),               \
                   e4 + (size_t)tixg * 4 + sub_);                            \
        CP_COMMIT();                                                         \
    }

    // Prologue: stages 0, 1, 2 in flight (register-addressed, pre-barrier)
    GATHER(0);
    GATHER(1);
    GATHER(2);

    __syncthreads();   // s_inp4 + s_box visible

    const int p_lo = lane >> 2;     // points p_lo and p_lo+8
    const int dsub = lane & 3;      // float4 dim group
    const bool full = (r0 + NRAY <= R);

    const int pi_[8] = {0, 1, 2, 0, 1, 2, 3, 3};
    const int zi_[8] = {0, 0, 0, 1, 1, 1, 0, 1};

    #pragma unroll
    for (int j = 0; j < NRAY; j++) {
        // ---- launch stage j+3 gather ----
        if (j + 3 < NRAY) GATHER(j + 3);

        // ---- node box + coords for stage j (4 broadcast LDS.128) ----
        const float4 b0 = s_box[j][w][0];   // pmx,pmy,pmz,rex
        const float4 b1 = s_box[j][w][1];   // rey,rez,-,-
        const float4 c0 = s_inp4[j * 16 + p_lo];
        const float4 c1 = s_inp4[j * 16 + p_lo + 8];

        float P[2][4], Z[2][2];
        #pragma unroll
        for (int half = 0; half < 2; half++) {
            const float4 cc = half ? c1 : c0;
            float x = fminf(fmaxf((cc.x - b0.x) * b0.w, 0.0f), 1.0f);
            float y = fminf(fmaxf((cc.y - b0.y) * b1.x, 0.0f), 1.0f);
            float z = fminf(fmaxf((cc.z - b0.z) * b1.y, 0.0f), 1.0f);
            const float ix = 1.0f - x, iy = 1.0f - y;
            P[half][0] = ix * iy;  P[half][1] = x * iy;
            P[half][2] = ix * y;   P[half][3] = x * y;
            Z[half][0] = (1.0f - z) * act;
            Z[half][1] = z * act;
        }

        // ---- wait for stage j's gather (leave j+1..j+3 in flight) ----
        if (j + 3 < NRAY)      cp_wait<3>();
        else if (j + 2 < NRAY) cp_wait<2>();
        else if (j + 1 < NRAY) cp_wait<1>();
        else                   cp_wait<0>();
        __syncwarp();

        float4 alo = make_float4(0.f, 0.f, 0.f, 0.f);
        float4 ahi = make_float4(0.f, 0.f, 0.f, 0.f);
        #pragma unroll
        for (int c = 0; c < 8; c++) {
            const float4 f  = sfeat[w][j & 3][c * 4 + dsub];
            const float  wl = P[0][pi_[c]] * Z[0][zi_[c]];
            const float  wh = P[1][pi_[c]] * Z[1][zi_[c]];
            alo.x = fmaf(wl, f.x, alo.x);
            alo.y = fmaf(wl, f.y, alo.y);
            alo.z = fmaf(wl, f.z, alo.z);
            alo.w = fmaf(wl, f.w, alo.w);
            ahi.x = fmaf(wh, f.x, ahi.x);
            ahi.y = fmaf(wh, f.y, ahi.y);
            ahi.z = fmaf(wh, f.z, ahi.z);
            ahi.w = fmaf(wh, f.w, ahi.w);
        }

        if (full || (r0 + j < R)) {
            float4* o = reinterpret_cast<float4*>(out)
                        + ((size_t)(r0 + j) * 8 + w) * 64;
            o[lane]      = alo;
            o[32 + lane] = ahi;
        }

        asm volatile("" ::: "memory");
    }
#undef GATHER
}

// ---------------------------------------------------------------------------
extern "C" void kernel_launch(void* const* d_in, const int* in_sizes, int n_in,
                              void* d_out, int out_size) {
    const float* inp     = (const float*)d_in[0];
    const int*   history = (const int*)d_in[1];
    const int*   depth   = (const int*)d_in[2];
    const float* nmin    = (const float*)d_in[3];
    const float* next    = (const float*)d_in[4];
    const float* emb     = (const float*)d_in[5];
    float*       out     = (float*)d_out;

    const int R = in_sizes[2];   // number of rays (= depth element count)

    depth_reduce_kernel<<<NRED, 256>>>(depth, R);
    nbvh_main_kernel<<<(R + NRAY - 1) / NRAY, 256>>>(
        inp, history, nmin, next, emb, out, R);
}

// round 16
// speedup vs baseline: 1.4859x; 1.4859x over previous
#include <cuda_runtime.h>
#include <stdint.h>

#define TABLE_MASK 0x7FFFFu
#define NRED 32
#define FULLM 0xffffffffu
#define NRAY 8

// Low 19 bits of ((c+1) * PIS[c]) — the only bits that matter for
// tidx = (idx ^ PP) & (2^19-1), since idx >= 0 and XOR is bitwise.
__constant__ unsigned c_ppl[8] = {
    (unsigned)(774363409ull   & 0x7FFFFull),
    (unsigned)(5308871522ull  & 0x7FFFFull),
    (unsigned)(2416379583ull  & 0x7FFFFull),
    (unsigned)(400000028ull   & 0x7FFFFull),
    (unsigned)(1671816955ull  & 0x7FFFFull),
    (unsigned)(8006180478ull  & 0x7FFFFull),
    (unsigned)(5140543849ull  & 0x7FFFFull),
    (unsigned)(17074907144ull & 0x7FFFFull)
};

static __device__ int g_partial[NRED];
static __device__ int g_activeL;
static __device__ unsigned g_ticket;

#define CP_ASYNC16(dst_smem, src_gmem)                                   \
    asm volatile("cp.async.cg.shared.global [%0], [%1], 16;"             \
                 :: "r"(dst_smem), "l"(src_gmem))
#define CP_COMMIT() asm volatile("cp.async.commit_group;" ::: "memory")
template <int N>
__device__ __forceinline__ void cp_wait() {
    asm volatile("cp.async.wait_group %0;" :: "n"(N) : "memory");
}

// ---------------------------------------------------------------------------
// Kernel 1: grid max over depth -> g_activeL (last block folds partials)
// ---------------------------------------------------------------------------
__global__ void depth_reduce_kernel(const int* __restrict__ depth, int n) {
    int m = 0;
    for (int i = blockIdx.x * blockDim.x + threadIdx.x; i < n;
         i += gridDim.x * blockDim.x)
        m = max(m, depth[i]);
    #pragma unroll
    for (int s = 16; s > 0; s >>= 1)
        m = max(m, __shfl_xor_sync(FULLM, m, s));
    __shared__ int sm[32];
    __shared__ bool last;
    int w = threadIdx.x >> 5;
    if ((threadIdx.x & 31) == 0) sm[w] = m;
    __syncthreads();
    if (threadIdx.x == 0) {
        int nw = (blockDim.x + 31) >> 5;
        int mm = sm[0];
        for (int i = 1; i < nw; i++) mm = max(mm, sm[i]);
        g_partial[blockIdx.x] = mm;
        __threadfence();
        unsigned t = atomicAdd(&g_ticket, 1u);
        last = (t == (unsigned)(gridDim.x - 1));
    }
    __syncthreads();
    if (last && threadIdx.x < 32) {
        int mm = g_partial[threadIdx.x];
        #pragma unroll
        for (int s = 16; s > 0; s >>= 1)
            mm = max(mm, __shfl_xor_sync(FULLM, mm, s));
        if (threadIdx.x == 0) {
            g_activeL = (mm < 8) ? mm : 8;
            g_ticket = 0;                 // reset for graph replay
        }
    }
}

// ---------------------------------------------------------------------------
// Kernel 2: main encoding, NRAY=8 rays/block, warp = level.
// Feature gather via cp.async into a 4-slot smem ring, prefetch depth 2.
// Node boxes (with reciprocals) and padded coords staged ONCE per block into
// smem; steady state reads them as 4 broadcast LDS.128 per stage instead of
// 12 scalar LDG/LDS — per-stage L1 wavefronts at the mandatory floor.
// Verified optimum: occ-7 thrashes L2, NRAY-16 hits wave quantization,
// depth-3 saturates the LSU fill queue, smem-idx adds LDS to the address
// path. Do not perturb without new evidence.
// ---------------------------------------------------------------------------
__global__ void __launch_bounds__(256, 6) nbvh_main_kernel(
    const float* __restrict__ inp,          // [R,16,3]
    const int*   __restrict__ history,      // [R,64]
    const float* __restrict__ nodes_min,    // [N,3]
    const float* __restrict__ nodes_extent, // [N,3]
    const float* __restrict__ emb,          // [524288,16]
    float* __restrict__ out,                // [R, 8*16*16]
    int R)
{
    __shared__ float4 sfeat[8][4][32];     // [warp][ring][corner*4+dim_group]
    __shared__ float4 s_inp4[NRAY * 16];   // [ray*16 + point] = {x,y,z,_}
    __shared__ float4 s_box[NRAY][8][2];   // [ray][level]

    const int tid  = threadIdx.x;
    const int w    = tid >> 5;       // level l
    const int lane = tid & 31;
    const int r0   = blockIdx.x * NRAY;

    // --- stage coords: thread t < 128 handles one point, padded to float4 ---
    if (tid < NRAY * 16) {
        int rj = r0 + (tid >> 4); if (rj >= R) rj = R - 1;
        const float* src = inp + (size_t)rj * 48 + (tid & 15) * 3;
        s_inp4[tid] = make_float4(src[0], src[1], src[2], 0.0f);
    }
    // --- stage node boxes: thread t < 64 handles one (ray, level) pair ---
    if (tid < NRAY * 8) {
        const int j = tid >> 3, lv = tid & 7;
        int rj = r0 + j; if (rj >= R) rj = R - 1;
        const int bi = history[rj * 64 + lv];
        const float* nm = nodes_min    + (size_t)bi * 3;
        const float* ne = nodes_extent + (size_t)bi * 3;
        s_box[j][lv][0] = make_float4(nm[0], nm[1], nm[2],
                                      __fdividef(1.0f, ne[0]));
        s_box[j][lv][1] = make_float4(__fdividef(1.0f, ne[1]),
                                      __fdividef(1.0f, ne[2]), 0.0f, 0.0f);
    }

    const int activeL = g_activeL;     // uniform scalar
    const float act   = (w < activeL) ? 1.0f : 0.0f;

    // All NRAY history indices up-front (MLP=8), register-resident —
    // keeps the cp.async address path free of LDS latency.
    int idxs[NRAY];
    #pragma unroll
    for (int j = 0; j < NRAY; j++) {
        int rj = r0 + j; if (rj >= R) rj = R - 1;
        idxs[j] = history[rj * 64 + w];
    }

    const int c_   = lane >> 2;      // corner for gather
    const int sub_ = lane & 3;       // float4 sub for gather
    const unsigned ppl = c_ppl[c_];  // low-19-bit hash constant
    const float4* e4 = reinterpret_cast<const float4*>(emb);

    const unsigned smem_lane_base =
        (unsigned)__cvta_generic_to_shared(&sfeat[w][0][lane]);
#define GATHER(stage)                                                        \
    {                                                                        \
        const unsigned tixg = ((unsigned)idxs[stage] ^ ppl) & TABLE_MASK;    \
        CP_ASYNC16(smem_lane_base + ((stage) & 3) * (32 * 16),               \
                   e4 + (size_t)tixg * 4 + sub_);                            \
        CP_COMMIT();                                                         \
    }

    // Prologue: stages 0 and 1 in flight (register-addressed, pre-barrier)
    GATHER(0);
    GATHER(1);

    __syncthreads();   // s_inp4 + s_box visible

    const int p_lo = lane >> 2;     // points p_lo and p_lo+8
    const int dsub = lane & 3;      // float4 dim group
    const bool full = (r0 + NRAY <= R);

    const int pi_[8] = {0, 1, 2, 0, 1, 2, 3, 3};
    const int zi_[8] = {0, 0, 0, 1, 1, 1, 0, 1};

    #pragma unroll
    for (int j = 0; j < NRAY; j++) {
        // ---- launch stage j+2 gather ----
        if (j + 2 < NRAY) GATHER(j + 2);

        // ---- node box + coords for stage j (4 broadcast LDS.128) ----
        const float4 b0 = s_box[j][w][0];   // pmx,pmy,pmz,rex
        const float4 b1 = s_box[j][w][1];   // rey,rez,-,-
        const float4 c0 = s_inp4[j * 16 + p_lo];
        const float4 c1 = s_inp4[j * 16 + p_lo + 8];

        float P[2][4], Z[2][2];
        #pragma unroll
        for (int half = 0; half < 2; half++) {
            const float4 cc = half ? c1 : c0;
            float x = fminf(fmaxf((cc.x - b0.x) * b0.w, 0.0f), 1.0f);
            float y = fminf(fmaxf((cc.y - b0.y) * b1.x, 0.0f), 1.0f);
            float z = fminf(fmaxf((cc.z - b0.z) * b1.y, 0.0f), 1.0f);
            const float ix = 1.0f - x, iy = 1.0f - y;
            P[half][0] = ix * iy;  P[half][1] = x * iy;
            P[half][2] = ix * y;   P[half][3] = x * y;
            Z[half][0] = (1.0f - z) * act;
            Z[half][1] = z * act;
        }

        // ---- wait for stage j's gather (leave j+1, j+2 in flight) ----
        if (j + 2 < NRAY)      cp_wait<2>();
        else if (j + 1 < NRAY) cp_wait<1>();
        else                   cp_wait<0>();
        __syncwarp();

        float4 alo = make_float4(0.f, 0.f, 0.f, 0.f);
        float4 ahi = make_float4(0.f, 0.f, 0.f, 0.f);
        #pragma unroll
        for (int c = 0; c < 8; c++) {
            const float4 f  = sfeat[w][j & 3][c * 4 + dsub];
            const float  wl = P[0][pi_[c]] * Z[0][zi_[c]];
            const float  wh = P[1][pi_[c]] * Z[1][zi_[c]];
            alo.x = fmaf(wl, f.x, alo.x);
            alo.y = fmaf(wl, f.y, alo.y);
            alo.z = fmaf(wl, f.z, alo.z);
            alo.w = fmaf(wl, f.w, alo.w);
            ahi.x = fmaf(wh, f.x, ahi.x);
            ahi.y = fmaf(wh, f.y, ahi.y);
            ahi.z = fmaf(wh, f.z, ahi.z);
            ahi.w = fmaf(wh, f.w, ahi.w);
        }

        if (full || (r0 + j < R)) {
            float4* o = reinterpret_cast<float4*>(out)
                        + ((size_t)(r0 + j) * 8 + w) * 64;
            o[lane]      = alo;
            o[32 + lane] = ahi;
        }

        // ring slot j&3 reused earliest by stage j+4 (issued at iter j+2):
        // depth-2 is WAR-safe
        asm volatile("" ::: "memory");
    }
#undef GATHER
}

// ---------------------------------------------------------------------------
extern "C" void kernel_launch(void* const* d_in, const int* in_sizes, int n_in,
                              void* d_out, int out_size) {
    const float* inp     = (const float*)d_in[0];
    const int*   history = (const int*)d_in[1];
    const int*   depth   = (const int*)d_in[2];
    const float* nmin    = (const float*)d_in[3];
    const float* next    = (const float*)d_in[4];
    const float* emb     = (const float*)d_in[5];
    float*       out     = (float*)d_out;

    const int R = in_sizes[2];   // number of rays (= depth element count)

    depth_reduce_kernel<<<NRED, 256>>>(depth, R);
    nbvh_main_kernel<<<(R + NRAY - 1) / NRAY, 256>>>(
        inp, history, nmin, next, emb, out, R);
}

// round 17
// speedup vs baseline: 1.5343x; 1.0325x over previous
#include <cuda_runtime.h>
#include <stdint.h>

#define TABLE_MASK 0x7FFFFu
#define NRED 32
#define FULLM 0xffffffffu
#define NRAY 8

// Low 19 bits of ((c+1) * PIS[c]) — the only bits that matter for
// tidx = (idx ^ PP) & (2^19-1), since idx >= 0 and XOR is bitwise.
__constant__ unsigned c_ppl[8] = {
    (unsigned)(774363409ull   & 0x7FFFFull),
    (unsigned)(5308871522ull  & 0x7FFFFull),
    (unsigned)(2416379583ull  & 0x7FFFFull),
    (unsigned)(400000028ull   & 0x7FFFFull),
    (unsigned)(1671816955ull  & 0x7FFFFull),
    (unsigned)(8006180478ull  & 0x7FFFFull),
    (unsigned)(5140543849ull  & 0x7FFFFull),
    (unsigned)(17074907144ull & 0x7FFFFull)
};

static __device__ int g_partial[NRED];
static __device__ int g_activeL;
static __device__ unsigned g_ticket;

#define CP_ASYNC16(dst_smem, src_gmem)                                   \
    asm volatile("cp.async.cg.shared.global [%0], [%1], 16;"             \
                 :: "r"(dst_smem), "l"(src_gmem))
#define CP_COMMIT() asm volatile("cp.async.commit_group;" ::: "memory")
template <int N>
__device__ __forceinline__ void cp_wait() {
    asm volatile("cp.async.wait_group %0;" :: "n"(N) : "memory");
}

// ---------------------------------------------------------------------------
// Kernel 1: grid max over depth -> g_activeL. Vectorized int4 loads (one 16B
// load per thread for R=32768), warp-shuffle reduce, last-block ticket fold.
// ---------------------------------------------------------------------------
__global__ void depth_reduce_kernel(const int* __restrict__ depth, int n) {
    const int n4 = n >> 2;
    const int4* d4 = reinterpret_cast<const int4*>(depth);
    int m = 0;
    for (int i = blockIdx.x * blockDim.x + threadIdx.x; i < n4;
         i += gridDim.x * blockDim.x) {
        const int4 v = d4[i];
        m = max(m, max(max(v.x, v.y), max(v.z, v.w)));
    }
    // scalar tail (n not divisible by 4)
    for (int i = (n4 << 2) + blockIdx.x * blockDim.x + threadIdx.x; i < n;
         i += gridDim.x * blockDim.x)
        m = max(m, depth[i]);

    #pragma unroll
    for (int s = 16; s > 0; s >>= 1)
        m = max(m, __shfl_xor_sync(FULLM, m, s));
    __shared__ int sm[32];
    __shared__ bool last;
    int w = threadIdx.x >> 5;
    if ((threadIdx.x & 31) == 0) sm[w] = m;
    __syncthreads();
    if (threadIdx.x == 0) {
        int nw = (blockDim.x + 31) >> 5;
        int mm = sm[0];
        for (int i = 1; i < nw; i++) mm = max(mm, sm[i]);
        g_partial[blockIdx.x] = mm;
        __threadfence();
        unsigned t = atomicAdd(&g_ticket, 1u);
        last = (t == (unsigned)(gridDim.x - 1));
    }
    __syncthreads();
    if (last && threadIdx.x < 32) {
        int mm = g_partial[threadIdx.x];
        #pragma unroll
        for (int s = 16; s > 0; s >>= 1)
            mm = max(mm, __shfl_xor_sync(FULLM, mm, s));
        if (threadIdx.x == 0) {
            g_activeL = (mm < 8) ? mm : 8;
            g_ticket = 0;                 // reset for graph replay
        }
    }
}

// ---------------------------------------------------------------------------
// Kernel 2: main encoding, NRAY=8 rays/block, warp = level.
// Feature gather via cp.async into a 4-slot smem ring, prefetch depth 2.
// Node boxes (with reciprocals) and padded coords staged ONCE per block into
// smem; steady state reads them as 4 broadcast LDS.128 per stage — at the
// mandatory L1 wavefront floor.
// Verified optimum (do not perturb without new evidence): occ-7 thrashes L2,
// NRAY-16 hits wave quantization, depth-3 saturates the LSU fill queue,
// smem-idx adds LDS to the cp.async address path.
// ---------------------------------------------------------------------------
__global__ void __launch_bounds__(256, 6) nbvh_main_kernel(
    const float* __restrict__ inp,          // [R,16,3]
    const int*   __restrict__ history,      // [R,64]
    const float* __restrict__ nodes_min,    // [N,3]
    const float* __restrict__ nodes_extent, // [N,3]
    const float* __restrict__ emb,          // [524288,16]
    float* __restrict__ out,                // [R, 8*16*16]
    int R)
{
    __shared__ float4 sfeat[8][4][32];     // [warp][ring][corner*4+dim_group]
    __shared__ float4 s_inp4[NRAY * 16];   // [ray*16 + point] = {x,y,z,_}
    __shared__ float4 s_box[NRAY][8][2];   // [ray][level]

    const int tid  = threadIdx.x;
    const int w    = tid >> 5;       // level l
    const int lane = tid & 31;
    const int r0   = blockIdx.x * NRAY;

    // --- stage coords: thread t < 128 handles one point, padded to float4 ---
    if (tid < NRAY * 16) {
        int rj = r0 + (tid >> 4); if (rj >= R) rj = R - 1;
        const float* src = inp + (size_t)rj * 48 + (tid & 15) * 3;
        s_inp4[tid] = make_float4(src[0], src[1], src[2], 0.0f);
    }
    // --- stage node boxes: thread t < 64 handles one (ray, level) pair ---
    if (tid < NRAY * 8) {
        const int j = tid >> 3, lv = tid & 7;
        int rj = r0 + j; if (rj >= R) rj = R - 1;
        const int bi = history[rj * 64 + lv];
        const float* nm = nodes_min    + (size_t)bi * 3;
        const float* ne = nodes_extent + (size_t)bi * 3;
        s_box[j][lv][0] = make_float4(nm[0], nm[1], nm[2],
                                      __fdividef(1.0f, ne[0]));
        s_box[j][lv][1] = make_float4(__fdividef(1.0f, ne[1]),
                                      __fdividef(1.0f, ne[2]), 0.0f, 0.0f);
    }

    const int activeL = g_activeL;     // uniform scalar
    const float act   = (w < activeL) ? 1.0f : 0.0f;

    // All NRAY history indices up-front (MLP=8), register-resident —
    // keeps the cp.async address path free of LDS latency.
    int idxs[NRAY];
    #pragma unroll
    for (int j = 0; j < NRAY; j++) {
        int rj = r0 + j; if (rj >= R) rj = R - 1;
        idxs[j] = history[rj * 64 + w];
    }

    const int c_   = lane >> 2;      // corner for gather
    const int sub_ = lane & 3;       // float4 sub for gather
    const unsigned ppl = c_ppl[c_];  // low-19-bit hash constant
    const float4* e4 = reinterpret_cast<const float4*>(emb);

    const unsigned smem_lane_base =
        (unsigned)__cvta_generic_to_shared(&sfeat[w][0][lane]);
#define GATHER(stage)                                                        \
    {                                                                        \
        const unsigned tixg = ((unsigned)idxs[stage] ^ ppl) & TABLE_MASK;    \
        CP_ASYNC16(smem_lane_base + ((stage) & 3) * (32 * 16),               \
                   e4 + (size_t)tixg * 4 + sub_);                            \
        CP_COMMIT();                                                         \
    }

    // Prologue: stages 0 and 1 in flight (register-addressed, pre-barrier)
    GATHER(0);
    GATHER(1);

    __syncthreads();   // s_inp4 + s_box visible

    const int p_lo = lane >> 2;     // points p_lo and p_lo+8
    const int dsub = lane & 3;      // float4 dim group
    const bool full = (r0 + NRAY <= R);

    const int pi_[8] = {0, 1, 2, 0, 1, 2, 3, 3};
    const int zi_[8] = {0, 0, 0, 1, 1, 1, 0, 1};

    #pragma unroll
    for (int j = 0; j < NRAY; j++) {
        // ---- launch stage j+2 gather ----
        if (j + 2 < NRAY) GATHER(j + 2);

        // ---- node box + coords for stage j (4 broadcast LDS.128) ----
        const float4 b0 = s_box[j][w][0];   // pmx,pmy,pmz,rex
        const float4 b1 = s_box[j][w][1];   // rey,rez,-,-
        const float4 c0 = s_inp4[j * 16 + p_lo];
        const float4 c1 = s_inp4[j * 16 + p_lo + 8];

        float P[2][4], Z[2][2];
        #pragma unroll
        for (int half = 0; half < 2; half++) {
            const float4 cc = half ? c1 : c0;
            float x = fminf(fmaxf((cc.x - b0.x) * b0.w, 0.0f), 1.0f);
            float y = fminf(fmaxf((cc.y - b0.y) * b1.x, 0.0f), 1.0f);
            float z = fminf(fmaxf((cc.z - b0.z) * b1.y, 0.0f), 1.0f);
            const float ix = 1.0f - x, iy = 1.0f - y;
            P[half][0] = ix * iy;  P[half][1] = x * iy;
            P[half][2] = ix * y;   P[half][3] = x * y;
            Z[half][0] = (1.0f - z) * act;
            Z[half][1] = z * act;
        }

        // ---- wait for stage j's gather (leave j+1, j+2 in flight) ----
        if (j + 2 < NRAY)      cp_wait<2>();
        else if (j + 1 < NRAY) cp_wait<1>();
        else                   cp_wait<0>();
        __syncwarp();

        float4 alo = make_float4(0.f, 0.f, 0.f, 0.f);
        float4 ahi = make_float4(0.f, 0.f, 0.f, 0.f);
        #pragma unroll
        for (int c = 0; c < 8; c++) {
            const float4 f  = sfeat[w][j & 3][c * 4 + dsub];
            const float  wl = P[0][pi_[c]] * Z[0][zi_[c]];
            const float  wh = P[1][pi_[c]] * Z[1][zi_[c]];
            alo.x = fmaf(wl, f.x, alo.x);
            alo.y = fmaf(wl, f.y, alo.y);
            alo.z = fmaf(wl, f.z, alo.z);
            alo.w = fmaf(wl, f.w, alo.w);
            ahi.x = fmaf(wh, f.x, ahi.x);
            ahi.y = fmaf(wh, f.y, ahi.y);
            ahi.z = fmaf(wh, f.z, ahi.z);
            ahi.w = fmaf(wh, f.w, ahi.w);
        }

        if (full || (r0 + j < R)) {
            float4* o = reinterpret_cast<float4*>(out)
                        + ((size_t)(r0 + j) * 8 + w) * 64;
            o[lane]      = alo;
            o[32 + lane] = ahi;
        }

        // ring slot j&3 reused earliest by stage j+4 (issued at iter j+2):
        // depth-2 is WAR-safe
        asm volatile("" ::: "memory");
    }
#undef GATHER
}

// ---------------------------------------------------------------------------
extern "C" void kernel_launch(void* const* d_in, const int* in_sizes, int n_in,
                              void* d_out, int out_size) {
    const float* inp     = (const float*)d_in[0];
    const int*   history = (const int*)d_in[1];
    const int*   depth   = (const int*)d_in[2];
    const float* nmin    = (const float*)d_in[3];
    const float* next    = (const float*)d_in[4];
    const float* emb     = (const float*)d_in[5];
    float*       out     = (float*)d_out;

    const int R = in_sizes[2];   // number of rays (= depth element count)

    depth_reduce_kernel<<<NRED, 256>>>(depth, R);
    nbvh_main_kernel<<<(R + NRAY - 1) / NRAY, 256>>>(
        inp, history, nmin, next, emb, out, R);
}